// round 8
// baseline (speedup 1.0000x reference)
#include <cuda_runtime.h>
#include <stdint.h>

#define NB 4
#define NN 512
#define DD 128
#define H1C 64
#define H2C 32
#define NT 8                       // 512/64 tiles
#define NPAIRS (NT * (NT + 1) / 2) // 36
#define THREADS 512

// ---- dynamic shared memory layout (bytes) ----
#define OFF_VIH  0                 // 64*68*4 = 17408
#define OFF_VJH  17408
#define OFF_W1F  34816             // 8 ks x 32 lane x 16 u32 = 16384
#define OFF_W2F  51200             // 4 ks x 32 lane x 8 u32 = 4096
#define SMEM_TOTAL 55296

// per-(batch, stripe) completion counters; zero-initialized, reset each run
__device__ int g_stripe_cnt[NB][NT];

static __device__ __forceinline__ uint32_t packh2(float lo, float hi) {
    uint32_t u;
    asm("cvt.rn.f16x2.f32 %0, %1, %2;" : "=r"(u) : "f"(hi), "f"(lo));
    return u;
}
static __device__ __forceinline__ uint32_t habs2_sub(uint32_t a, uint32_t b) {
    uint32_t d;
    asm("sub.f16x2 %0, %1, %2;" : "=r"(d) : "r"(a), "r"(b));
    return d & 0x7FFF7FFFu;
}
static __device__ __forceinline__ void mma_f16(float* c,
        uint32_t a0, uint32_t a1, uint32_t a2, uint32_t a3,
        uint32_t b0, uint32_t b1) {
    asm volatile(
        "mma.sync.aligned.m16n8k16.row.col.f32.f16.f16.f32 "
        "{%0,%1,%2,%3}, {%4,%5,%6,%7}, {%8,%9}, {%0,%1,%2,%3};"
        : "+f"(c[0]), "+f"(c[1]), "+f"(c[2]), "+f"(c[3])
        : "r"(a0), "r"(a1), "r"(a2), "r"(a3), "r"(b0), "r"(b1));
}
static __device__ __forceinline__ float leaky(float x) { return fmaxf(x, 0.1f * x); }

// ---------------------------------------------------------------------------
// Fused kernel: symmetric fp16-HMMA logits + counter-gated stripe softmax.
// CTA = (batch, tile-pair ti<=tj, 64x64).  All 144 CTAs co-resident.
// ---------------------------------------------------------------------------
__global__ __launch_bounds__(THREADS, 1)
void adj_fused_kernel(const float* __restrict__ v,
                      const float* __restrict__ W1, const float* __restrict__ b1,
                      const float* __restrict__ W2, const float* __restrict__ b2,
                      const float* __restrict__ W3, const float* __restrict__ b3,
                      float* __restrict__ out)
{
    extern __shared__ char sm[];
    uint32_t* VIh = (uint32_t*)(sm + OFF_VIH);
    uint32_t* VJh = (uint32_t*)(sm + OFF_VJH);
    uint32_t* W1F = (uint32_t*)(sm + OFF_W1F);
    uint32_t* W2F = (uint32_t*)(sm + OFF_W2F);

    const int tid  = threadIdx.x;
    const int wid  = tid >> 5;
    const int lane = tid & 31;
    const int g    = lane >> 2;   // groupID (row within fragment)
    const int t    = lane & 3;    // threadID_in_group
    const int b    = blockIdx.y;

    // decode (ti, tj), ti <= tj
    int rem = blockIdx.x;
    int ti = 0;
    while (rem >= NT - ti) { rem -= NT - ti; ti++; }
    const int tj = ti + rem;

    // ---- load v tiles (64 x 128 fp32), convert to half2, rows padded to 68 u32 ----
    const float* vb = v + (size_t)b * NN * DD;
    for (int e = tid; e < 64 * 32; e += THREADS) {
        int r = e >> 5, c = e & 31;
        float4 xi = ((const float4*)(vb + (size_t)(ti * 64 + r) * DD))[c];
        float4 xj = ((const float4*)(vb + (size_t)(tj * 64 + r) * DD))[c];
        VIh[r * 68 + 2 * c]     = packh2(xi.x, xi.y);
        VIh[r * 68 + 2 * c + 1] = packh2(xi.z, xi.w);
        VJh[r * 68 + 2 * c]     = packh2(xj.x, xj.y);
        VJh[r * 68 + 2 * c + 1] = packh2(xj.z, xj.w);
    }
    // ---- W1 half2 fragments: [ks(8)][lane(32)][n(8)x{b0,b1}] ----
    for (int idx = tid; idx < 8 * 32 * 16; idx += THREADS) {
        int ks = idx >> 9, ln = (idx >> 4) & 31, rm = idx & 15;
        int n = rm >> 1, e = rm & 1;
        int o  = (ln >> 2) + 8 * n;
        int kb = 16 * ks + 2 * (ln & 3) + 8 * e;
        W1F[idx] = packh2(W1[o * DD + kb], W1[o * DD + kb + 1]);
    }
    // ---- W2 half2 fragments: [ks(4)][lane(32)][n(4)x{b0,b1}] ----
    for (int idx = tid; idx < 4 * 32 * 8; idx += THREADS) {
        int ks = idx >> 8, ln = (idx >> 3) & 31, rm = idx & 7;
        int n = rm >> 1, e = rm & 1;
        int o  = (ln >> 2) + 8 * n;
        int kb = 16 * ks + 2 * (ln & 3) + 8 * e;
        W2F[idx] = packh2(W2[o * H1C + kb], W2[o * H1C + kb + 1]);
    }
    // per-thread bias / w3 values at this thread's fragment columns
    float b1r[16], b2v[8], w3v[8];
    #pragma unroll
    for (int n = 0; n < 8; ++n) {
        b1r[2 * n]     = b1[8 * n + 2 * t];
        b1r[2 * n + 1] = b1[8 * n + 2 * t + 1];
    }
    #pragma unroll
    for (int n = 0; n < 4; ++n) {
        b2v[2 * n]     = b2[8 * n + 2 * t];
        b2v[2 * n + 1] = b2[8 * n + 2 * t + 1];
        w3v[2 * n]     = W3[8 * n + 2 * t];
        w3v[2 * n + 1] = W3[8 * n + 2 * t + 1];
    }
    const float bias3 = b3[0];
    __syncthreads();

    float* ob = out + (size_t)b * NN * NN;

    for (int ii = 0; ii < 4; ++ii) {
        const int il = wid * 4 + ii;
        const int ig = ti * 64 + il;

        uint32_t vilo[8], vihi[8];
        #pragma unroll
        for (int ks = 0; ks < 8; ++ks) {
            vilo[ks] = VIh[il * 68 + 8 * ks + t];
            vihi[ks] = VIh[il * 68 + 8 * ks + t + 4];
        }

        for (int jm = 0; jm < 4; ++jm) {
            const uint32_t* vj0 = VJh + (jm * 16 + g) * 68;
            const uint32_t* vj1 = VJh + (jm * 16 + 8 + g) * 68;

            // ---- GEMM1: h1[16j x 64] = |vi - vj| @ W1^T,  K = 128 ----
            float c1[8][4];
            #pragma unroll
            for (int n = 0; n < 8; ++n) {
                c1[n][0] = b1r[2 * n];     c1[n][1] = b1r[2 * n + 1];
                c1[n][2] = b1r[2 * n];     c1[n][3] = b1r[2 * n + 1];
            }
            #pragma unroll
            for (int ks = 0; ks < 8; ++ks) {
                uint32_t a0 = habs2_sub(vilo[ks], vj0[8 * ks + t]);
                uint32_t a1 = habs2_sub(vilo[ks], vj1[8 * ks + t]);
                uint32_t a2 = habs2_sub(vihi[ks], vj0[8 * ks + t + 4]);
                uint32_t a3 = habs2_sub(vihi[ks], vj1[8 * ks + t + 4]);
                const uint32_t* wq = W1F + ks * 512 + lane * 16;
                #pragma unroll
                for (int n = 0; n < 8; ++n)
                    mma_f16(c1[n], a0, a1, a2, a3, wq[2 * n], wq[2 * n + 1]);
            }

            // ---- GEMM2: h2 = leaky(h1) @ W2^T (identity re-fragmentation) ----
            float c2[4][4];
            #pragma unroll
            for (int n = 0; n < 4; ++n) {
                c2[n][0] = b2v[2 * n];     c2[n][1] = b2v[2 * n + 1];
                c2[n][2] = b2v[2 * n];     c2[n][3] = b2v[2 * n + 1];
            }
            #pragma unroll
            for (int ks = 0; ks < 4; ++ks) {
                uint32_t a0 = packh2(leaky(c1[2 * ks][0]),     leaky(c1[2 * ks][1]));
                uint32_t a1 = packh2(leaky(c1[2 * ks][2]),     leaky(c1[2 * ks][3]));
                uint32_t a2 = packh2(leaky(c1[2 * ks + 1][0]), leaky(c1[2 * ks + 1][1]));
                uint32_t a3 = packh2(leaky(c1[2 * ks + 1][2]), leaky(c1[2 * ks + 1][3]));
                const uint32_t* wq = W2F + ks * 256 + lane * 8;
                #pragma unroll
                for (int n = 0; n < 4; ++n)
                    mma_f16(c2[n], a0, a1, a2, a3, wq[2 * n], wq[2 * n + 1]);
            }

            // ---- layer 3 + quad reduction ----
            float p0 = 0.0f, p1 = 0.0f;
            #pragma unroll
            for (int n = 0; n < 4; ++n) {
                p0 += leaky(c2[n][0]) * w3v[2 * n];
                p0 += leaky(c2[n][1]) * w3v[2 * n + 1];
                p1 += leaky(c2[n][2]) * w3v[2 * n];
                p1 += leaky(c2[n][3]) * w3v[2 * n + 1];
            }
            p0 += __shfl_xor_sync(0xFFFFFFFFu, p0, 1);
            p0 += __shfl_xor_sync(0xFFFFFFFFu, p0, 2);
            p1 += __shfl_xor_sync(0xFFFFFFFFu, p1, 1);
            p1 += __shfl_xor_sync(0xFFFFFFFFu, p1, 2);

            if (t == 0) {
                const int jg = tj * 64 + jm * 16 + g;
                float v0 = p0 + bias3, v1 = p1 + bias3;
                ob[(size_t)ig * NN + jg]     = v0;
                ob[(size_t)ig * NN + jg + 8] = v1;
                if (ti != tj) {
                    ob[(size_t)jg * NN + ig]       = v0;
                    ob[(size_t)(jg + 8) * NN + ig] = v1;
                }
            }
        }
    }

    // ================= fused softmax: signal + (diag CTAs) consume =========
    __syncthreads();
    __threadfence();                      // make logit STGs visible device-wide
    if (tid == 0) {
        atomicAdd(&g_stripe_cnt[b][ti], 1);
        if (ti != tj) atomicAdd(&g_stripe_cnt[b][tj], 1);
    }

    if (ti == tj) {
        // owner of stripe (b, ti): wait for all 8 contributing CTAs
        if (tid == 0) {
            while (atomicAdd(&g_stripe_cnt[b][ti], 0) < 8) __nanosleep(64);
            __threadfence();              // acquire: order counter read before data reads
        }
        __syncthreads();

        // softmax over 64 rows; one warp per row, 4 rows per warp, shfl-only
        for (int r = 0; r < 4; ++r) {
            const int row = ti * 64 + wid * 4 + r;
            float4* p = (float4*)(ob + (size_t)row * NN);

            float4 x0 = p[lane];
            float4 x1 = p[lane + 32];
            float4 x2 = p[lane + 64];
            float4 x3 = p[lane + 96];

            float m = fmaxf(fmaxf(fmaxf(x0.x, x0.y), fmaxf(x0.z, x0.w)),
                            fmaxf(fmaxf(x1.x, x1.y), fmaxf(x1.z, x1.w)));
            m = fmaxf(m, fmaxf(fmaxf(fmaxf(x2.x, x2.y), fmaxf(x2.z, x2.w)),
                               fmaxf(fmaxf(x3.x, x3.y), fmaxf(x3.z, x3.w))));
            #pragma unroll
            for (int o = 16; o; o >>= 1) m = fmaxf(m, __shfl_xor_sync(0xFFFFFFFFu, m, o));

            x0.x = __expf(x0.x - m); x0.y = __expf(x0.y - m);
            x0.z = __expf(x0.z - m); x0.w = __expf(x0.w - m);
            x1.x = __expf(x1.x - m); x1.y = __expf(x1.y - m);
            x1.z = __expf(x1.z - m); x1.w = __expf(x1.w - m);
            x2.x = __expf(x2.x - m); x2.y = __expf(x2.y - m);
            x2.z = __expf(x2.z - m); x2.w = __expf(x2.w - m);
            x3.x = __expf(x3.x - m); x3.y = __expf(x3.y - m);
            x3.z = __expf(x3.z - m); x3.w = __expf(x3.w - m);

            float s = ((x0.x + x0.y) + (x0.z + x0.w)) + ((x1.x + x1.y) + (x1.z + x1.w))
                    + ((x2.x + x2.y) + (x2.z + x2.w)) + ((x3.x + x3.y) + (x3.z + x3.w));
            #pragma unroll
            for (int o = 16; o; o >>= 1) s += __shfl_xor_sync(0xFFFFFFFFu, s, o);

            float inv = __fdividef(1.0f, s);
            x0.x *= inv; x0.y *= inv; x0.z *= inv; x0.w *= inv;
            x1.x *= inv; x1.y *= inv; x1.z *= inv; x1.w *= inv;
            x2.x *= inv; x2.y *= inv; x2.z *= inv; x2.w *= inv;
            x3.x *= inv; x3.y *= inv; x3.z *= inv; x3.w *= inv;

            p[lane]      = x0;
            p[lane + 32] = x1;
            p[lane + 64] = x2;
            p[lane + 96] = x3;
        }

        // reset counter for the next graph replay
        __syncthreads();
        if (tid == 0) atomicExch(&g_stripe_cnt[b][ti], 0);
    }
}

extern "C" void kernel_launch(void* const* d_in, const int* in_sizes, int n_in,
                              void* d_out, int out_size)
{
    const float* v  = (const float*)d_in[0];
    const float* W1 = (const float*)d_in[1];
    const float* b1 = (const float*)d_in[2];
    const float* W2 = (const float*)d_in[3];
    const float* b2 = (const float*)d_in[4];
    const float* W3 = (const float*)d_in[5];
    const float* b3 = (const float*)d_in[6];
    float* out = (float*)d_out;

    cudaFuncSetAttribute(adj_fused_kernel,
                         cudaFuncAttributeMaxDynamicSharedMemorySize, SMEM_TOTAL);

    dim3 grid(NPAIRS, NB);   // (36, 4) — 144 CTAs, all co-resident (1 wave)
    adj_fused_kernel<<<grid, THREADS, SMEM_TOTAL>>>(v, W1, b1, W2, b2, W3, b3, out);
}

// round 9
// speedup vs baseline: 1.7011x; 1.7011x over previous
#include <cuda_runtime.h>
#include <stdint.h>

#define NB 4
#define NN 512
#define DD 128
#define H1C 64
#define H2C 32
#define NT 8                       // 512/64 tiles
#define NPAIRS (NT * (NT + 1) / 2) // 36
#define THREADS 256

// ---- dynamic shared memory layout (bytes) ----
#define OFF_VIH  0                 // 64*68*4 = 17408
#define OFF_VJH  17408
#define OFF_W1F  34816             // 8 ks x 32 lane x 16 u32 = 16384
#define OFF_W2F  51200             // 4 ks x 32 lane x 8 u32 = 4096
#define SMEM_TOTAL 55296

static __device__ __forceinline__ uint32_t packh2(float lo, float hi) {
    uint32_t u;
    asm("cvt.rn.f16x2.f32 %0, %1, %2;" : "=r"(u) : "f"(hi), "f"(lo));
    return u;
}
static __device__ __forceinline__ uint32_t habs2_sub(uint32_t a, uint32_t b) {
    uint32_t d;
    asm("sub.f16x2 %0, %1, %2;" : "=r"(d) : "r"(a), "r"(b));
    return d & 0x7FFF7FFFu;
}
static __device__ __forceinline__ void mma_f16(float* c,
        uint32_t a0, uint32_t a1, uint32_t a2, uint32_t a3,
        uint32_t b0, uint32_t b1) {
    asm volatile(
        "mma.sync.aligned.m16n8k16.row.col.f32.f16.f16.f32 "
        "{%0,%1,%2,%3}, {%4,%5,%6,%7}, {%8,%9}, {%0,%1,%2,%3};"
        : "+f"(c[0]), "+f"(c[1]), "+f"(c[2]), "+f"(c[3])
        : "r"(a0), "r"(a1), "r"(a2), "r"(a3), "r"(b0), "r"(b1));
}
static __device__ __forceinline__ float leaky(float x) { return fmaxf(x, 0.1f * x); }

// ---------------------------------------------------------------------------
// Symmetric fp16-HMMA logits kernel, 2-i-row register blocking.
// CTA = (batch, tile-pair ti<=tj, 64x64).  8 warps x 256 threads; warp w
// owns i-rows w*8..w*8+7, processed in pairs so each weight/vj SMEM load
// feeds two MMAs (halves L1 wavefronts, doubles MMA ILP).
// ---------------------------------------------------------------------------
__global__ __launch_bounds__(THREADS, 1)
void adj_hmma_kernel(const float* __restrict__ v,
                     const float* __restrict__ W1, const float* __restrict__ b1,
                     const float* __restrict__ W2, const float* __restrict__ b2,
                     const float* __restrict__ W3, const float* __restrict__ b3,
                     float* __restrict__ out)
{
    extern __shared__ char sm[];
    uint32_t* VIh = (uint32_t*)(sm + OFF_VIH);
    uint32_t* VJh = (uint32_t*)(sm + OFF_VJH);
    uint32_t* W1F = (uint32_t*)(sm + OFF_W1F);
    uint32_t* W2F = (uint32_t*)(sm + OFF_W2F);

    const int tid  = threadIdx.x;
    const int wid  = tid >> 5;
    const int lane = tid & 31;
    const int g    = lane >> 2;   // groupID (row within fragment)
    const int t    = lane & 3;    // threadID_in_group
    const int b    = blockIdx.y;

    // decode (ti, tj), ti <= tj
    int rem = blockIdx.x;
    int ti = 0;
    while (rem >= NT - ti) { rem -= NT - ti; ti++; }
    const int tj = ti + rem;

    // ---- load v tiles (64 x 128 fp32), convert to half2, rows padded to 68 u32 ----
    const float* vb = v + (size_t)b * NN * DD;
    for (int e = tid; e < 64 * 32; e += THREADS) {
        int r = e >> 5, c = e & 31;
        float4 xi = ((const float4*)(vb + (size_t)(ti * 64 + r) * DD))[c];
        float4 xj = ((const float4*)(vb + (size_t)(tj * 64 + r) * DD))[c];
        VIh[r * 68 + 2 * c]     = packh2(xi.x, xi.y);
        VIh[r * 68 + 2 * c + 1] = packh2(xi.z, xi.w);
        VJh[r * 68 + 2 * c]     = packh2(xj.x, xj.y);
        VJh[r * 68 + 2 * c + 1] = packh2(xj.z, xj.w);
    }
    // ---- W1 half2 fragments: [ks(8)][lane(32)][n(8)x{b0,b1}] ----
    for (int idx = tid; idx < 8 * 32 * 16; idx += THREADS) {
        int ks = idx >> 9, ln = (idx >> 4) & 31, rm = idx & 15;
        int n = rm >> 1, e = rm & 1;
        int o  = (ln >> 2) + 8 * n;
        int kb = 16 * ks + 2 * (ln & 3) + 8 * e;
        W1F[idx] = packh2(W1[o * DD + kb], W1[o * DD + kb + 1]);
    }
    // ---- W2 half2 fragments: [ks(4)][lane(32)][n(4)x{b0,b1}] ----
    for (int idx = tid; idx < 4 * 32 * 8; idx += THREADS) {
        int ks = idx >> 8, ln = (idx >> 3) & 31, rm = idx & 7;
        int n = rm >> 1, e = rm & 1;
        int o  = (ln >> 2) + 8 * n;
        int kb = 16 * ks + 2 * (ln & 3) + 8 * e;
        W2F[idx] = packh2(W2[o * H1C + kb], W2[o * H1C + kb + 1]);
    }
    // per-thread bias / w3 values at this thread's fragment columns
    float b1r[16], b2v[8], w3v[8];
    #pragma unroll
    for (int n = 0; n < 8; ++n) {
        b1r[2 * n]     = b1[8 * n + 2 * t];
        b1r[2 * n + 1] = b1[8 * n + 2 * t + 1];
    }
    #pragma unroll
    for (int n = 0; n < 4; ++n) {
        b2v[2 * n]     = b2[8 * n + 2 * t];
        b2v[2 * n + 1] = b2[8 * n + 2 * t + 1];
        w3v[2 * n]     = W3[8 * n + 2 * t];
        w3v[2 * n + 1] = W3[8 * n + 2 * t + 1];
    }
    const float bias3 = b3[0];
    __syncthreads();

    float* ob = out + (size_t)b * NN * NN;

    for (int ip = 0; ip < 4; ++ip) {
        const int il0 = wid * 8 + ip * 2;     // first of the i-row pair
        const int ig0 = ti * 64 + il0;

        // hoist both i-rows' half2 values at this thread's k-positions
        uint32_t vlo0[8], vhi0[8], vlo1[8], vhi1[8];
        #pragma unroll
        for (int ks = 0; ks < 8; ++ks) {
            vlo0[ks] = VIh[il0 * 68 + 8 * ks + t];
            vhi0[ks] = VIh[il0 * 68 + 8 * ks + t + 4];
            vlo1[ks] = VIh[(il0 + 1) * 68 + 8 * ks + t];
            vhi1[ks] = VIh[(il0 + 1) * 68 + 8 * ks + t + 4];
        }

        for (int jm = 0; jm < 4; ++jm) {
            const uint32_t* vj0 = VJh + (jm * 16 + g) * 68;
            const uint32_t* vj1 = VJh + (jm * 16 + 8 + g) * 68;

            // ---- GEMM1 (both i-rows): h1 = |vi - vj| @ W1^T,  K = 128 ----
            float c10[8][4], c11[8][4];
            #pragma unroll
            for (int n = 0; n < 8; ++n) {
                c10[n][0] = b1r[2 * n];  c10[n][1] = b1r[2 * n + 1];
                c10[n][2] = b1r[2 * n];  c10[n][3] = b1r[2 * n + 1];
                c11[n][0] = b1r[2 * n];  c11[n][1] = b1r[2 * n + 1];
                c11[n][2] = b1r[2 * n];  c11[n][3] = b1r[2 * n + 1];
            }
            #pragma unroll
            for (int ks = 0; ks < 8; ++ks) {
                uint32_t j0l = vj0[8 * ks + t];
                uint32_t j1l = vj1[8 * ks + t];
                uint32_t j0h = vj0[8 * ks + t + 4];
                uint32_t j1h = vj1[8 * ks + t + 4];
                uint32_t a00 = habs2_sub(vlo0[ks], j0l);
                uint32_t a10 = habs2_sub(vlo0[ks], j1l);
                uint32_t a20 = habs2_sub(vhi0[ks], j0h);
                uint32_t a30 = habs2_sub(vhi0[ks], j1h);
                uint32_t a01 = habs2_sub(vlo1[ks], j0l);
                uint32_t a11 = habs2_sub(vlo1[ks], j1l);
                uint32_t a21 = habs2_sub(vhi1[ks], j0h);
                uint32_t a31 = habs2_sub(vhi1[ks], j1h);
                const uint32_t* wq = W1F + ks * 512 + lane * 16;
                #pragma unroll
                for (int n = 0; n < 8; ++n) {
                    uint32_t w0 = wq[2 * n], w1 = wq[2 * n + 1];
                    mma_f16(c10[n], a00, a10, a20, a30, w0, w1);
                    mma_f16(c11[n], a01, a11, a21, a31, w0, w1);
                }
            }

            // ---- GEMM2 (both i-rows): h2 = leaky(h1) @ W2^T,  K = 64 ----
            float c20[4][4], c21[4][4];
            #pragma unroll
            for (int n = 0; n < 4; ++n) {
                c20[n][0] = b2v[2 * n];  c20[n][1] = b2v[2 * n + 1];
                c20[n][2] = b2v[2 * n];  c20[n][3] = b2v[2 * n + 1];
                c21[n][0] = b2v[2 * n];  c21[n][1] = b2v[2 * n + 1];
                c21[n][2] = b2v[2 * n];  c21[n][3] = b2v[2 * n + 1];
            }
            #pragma unroll
            for (int ks = 0; ks < 4; ++ks) {
                uint32_t a00 = packh2(leaky(c10[2 * ks][0]),     leaky(c10[2 * ks][1]));
                uint32_t a10 = packh2(leaky(c10[2 * ks][2]),     leaky(c10[2 * ks][3]));
                uint32_t a20 = packh2(leaky(c10[2 * ks + 1][0]), leaky(c10[2 * ks + 1][1]));
                uint32_t a30 = packh2(leaky(c10[2 * ks + 1][2]), leaky(c10[2 * ks + 1][3]));
                uint32_t a01 = packh2(leaky(c11[2 * ks][0]),     leaky(c11[2 * ks][1]));
                uint32_t a11 = packh2(leaky(c11[2 * ks][2]),     leaky(c11[2 * ks][3]));
                uint32_t a21 = packh2(leaky(c11[2 * ks + 1][0]), leaky(c11[2 * ks + 1][1]));
                uint32_t a31 = packh2(leaky(c11[2 * ks + 1][2]), leaky(c11[2 * ks + 1][3]));
                const uint32_t* wq = W2F + ks * 256 + lane * 8;
                #pragma unroll
                for (int n = 0; n < 4; ++n) {
                    uint32_t w0 = wq[2 * n], w1 = wq[2 * n + 1];
                    mma_f16(c20[n], a00, a10, a20, a30, w0, w1);
                    mma_f16(c21[n], a01, a11, a21, a31, w0, w1);
                }
            }

            // ---- layer 3 + quad reductions, both i-rows ----
            float p00 = 0.0f, p01 = 0.0f, p10 = 0.0f, p11 = 0.0f;
            #pragma unroll
            for (int n = 0; n < 4; ++n) {
                p00 += leaky(c20[n][0]) * w3v[2 * n];
                p00 += leaky(c20[n][1]) * w3v[2 * n + 1];
                p01 += leaky(c20[n][2]) * w3v[2 * n];
                p01 += leaky(c20[n][3]) * w3v[2 * n + 1];
                p10 += leaky(c21[n][0]) * w3v[2 * n];
                p10 += leaky(c21[n][1]) * w3v[2 * n + 1];
                p11 += leaky(c21[n][2]) * w3v[2 * n];
                p11 += leaky(c21[n][3]) * w3v[2 * n + 1];
            }
            p00 += __shfl_xor_sync(0xFFFFFFFFu, p00, 1);
            p00 += __shfl_xor_sync(0xFFFFFFFFu, p00, 2);
            p01 += __shfl_xor_sync(0xFFFFFFFFu, p01, 1);
            p01 += __shfl_xor_sync(0xFFFFFFFFu, p01, 2);
            p10 += __shfl_xor_sync(0xFFFFFFFFu, p10, 1);
            p10 += __shfl_xor_sync(0xFFFFFFFFu, p10, 2);
            p11 += __shfl_xor_sync(0xFFFFFFFFu, p11, 1);
            p11 += __shfl_xor_sync(0xFFFFFFFFu, p11, 2);

            if (t == 0) {
                const int jg = tj * 64 + jm * 16 + g;
                float v00 = p00 + bias3, v01 = p01 + bias3;
                float v10 = p10 + bias3, v11 = p11 + bias3;
                ob[(size_t)ig0 * NN + jg]           = v00;
                ob[(size_t)ig0 * NN + jg + 8]       = v01;
                ob[(size_t)(ig0 + 1) * NN + jg]     = v10;
                ob[(size_t)(ig0 + 1) * NN + jg + 8] = v11;
                if (ti != tj) {   // mirror (logits exactly symmetric)
                    ob[(size_t)jg * NN + ig0]           = v00;
                    ob[(size_t)(jg + 8) * NN + ig0]     = v01;
                    ob[(size_t)jg * NN + ig0 + 1]       = v10;
                    ob[(size_t)(jg + 8) * NN + ig0 + 1] = v11;
                }
            }
        }
    }
}

// ---------------------------------------------------------------------------
// Row softmax over last axis. One block (128 thr) per (b, i); float4 I/O.
// ---------------------------------------------------------------------------
__global__ __launch_bounds__(128)
void adj_softmax_kernel(float* __restrict__ out)
{
    float4* __restrict__ p = (float4*)(out + (size_t)blockIdx.x * NN);
    const int tid = threadIdx.x;

    float4 x = p[tid];

    float m = fmaxf(fmaxf(x.x, x.y), fmaxf(x.z, x.w));
    #pragma unroll
    for (int o = 16; o; o >>= 1) m = fmaxf(m, __shfl_xor_sync(0xFFFFFFFFu, m, o));
    __shared__ float redm[4];
    if ((tid & 31) == 0) redm[tid >> 5] = m;
    __syncthreads();
    float M = fmaxf(fmaxf(redm[0], redm[1]), fmaxf(redm[2], redm[3]));

    float4 e;
    e.x = __expf(x.x - M);
    e.y = __expf(x.y - M);
    e.z = __expf(x.z - M);
    e.w = __expf(x.w - M);

    float s = (e.x + e.y) + (e.z + e.w);
    #pragma unroll
    for (int o = 16; o; o >>= 1) s += __shfl_xor_sync(0xFFFFFFFFu, s, o);
    __shared__ float reds[4];
    if ((tid & 31) == 0) reds[tid >> 5] = s;
    __syncthreads();
    float S = (reds[0] + reds[1]) + (reds[2] + reds[3]);

    float inv = __fdividef(1.0f, S);
    e.x *= inv; e.y *= inv; e.z *= inv; e.w *= inv;
    p[tid] = e;
}

extern "C" void kernel_launch(void* const* d_in, const int* in_sizes, int n_in,
                              void* d_out, int out_size)
{
    const float* v  = (const float*)d_in[0];
    const float* W1 = (const float*)d_in[1];
    const float* b1 = (const float*)d_in[2];
    const float* W2 = (const float*)d_in[3];
    const float* b2 = (const float*)d_in[4];
    const float* W3 = (const float*)d_in[5];
    const float* b3 = (const float*)d_in[6];
    float* out = (float*)d_out;

    cudaFuncSetAttribute(adj_hmma_kernel,
                         cudaFuncAttributeMaxDynamicSharedMemorySize, SMEM_TOTAL);

    dim3 grid(NPAIRS, NB);   // (36, 4) — one wave of 144 CTAs
    adj_hmma_kernel<<<grid, THREADS, SMEM_TOTAL>>>(v, W1, b1, W2, b2, W3, b3, out);
    adj_softmax_kernel<<<NB * NN, 128>>>(out);
}

// round 10
// speedup vs baseline: 2.1004x; 1.2347x over previous
#include <cuda_runtime.h>
#include <stdint.h>

#define NB 4
#define NN 512
#define DD 128
#define H1C 64
#define H2C 32
#define NT 8                       // 512/64 tiles
#define NPAIRS (NT * (NT + 1) / 2) // 36
#define THREADS 256

// ---- dynamic shared memory layout (bytes) ----
#define OFF_VIH  0                 // 64*68*4 = 17408
#define OFF_VJH  17408
#define OFF_W1F  34816             // 8 ks x 32 lane x 16 u32 = 16384
#define OFF_W2F  51200             // 4 ks x 32 lane x 8 u32 = 4096
#define OFF_B1S  55296             // 64 f
#define OFF_B2S  55552             // 32 f
#define OFF_W3S  55680             // 32 f
#define SMEM_TOTAL 55808

static __device__ __forceinline__ uint32_t packh2(float lo, float hi) {
    uint32_t u;
    asm("cvt.rn.f16x2.f32 %0, %1, %2;" : "=r"(u) : "f"(hi), "f"(lo));
    return u;
}
static __device__ __forceinline__ uint32_t habs2_sub(uint32_t a, uint32_t b) {
    uint32_t d;
    asm("sub.f16x2 %0, %1, %2;" : "=r"(d) : "r"(a), "r"(b));
    return d & 0x7FFF7FFFu;
}
static __device__ __forceinline__ void mma_f16(float* c,
        uint32_t a0, uint32_t a1, uint32_t a2, uint32_t a3,
        uint32_t b0, uint32_t b1) {
    asm volatile(
        "mma.sync.aligned.m16n8k16.row.col.f32.f16.f16.f32 "
        "{%0,%1,%2,%3}, {%4,%5,%6,%7}, {%8,%9}, {%0,%1,%2,%3};"
        : "+f"(c[0]), "+f"(c[1]), "+f"(c[2]), "+f"(c[3])
        : "r"(a0), "r"(a1), "r"(a2), "r"(a3), "r"(b0), "r"(b1));
}
static __device__ __forceinline__ float leaky(float x) { return fmaxf(x, 0.1f * x); }

// ---------------------------------------------------------------------------
// Symmetric fp16-HMMA logits kernel, 4-i-row register blocking.
// CTA = (batch, tile-pair ti<=tj, 64x64).  8 warps; warp w owns i-rows
// w*8..w*8+7, processed 4 at a time: each weight/vj SMEM load feeds FOUR
// MMAs.  GEMM2 + epilogue run in row-pairs to bound register pressure.
// ---------------------------------------------------------------------------
__global__ __launch_bounds__(THREADS, 1)
void adj_hmma_kernel(const float* __restrict__ v,
                     const float* __restrict__ W1, const float* __restrict__ b1,
                     const float* __restrict__ W2, const float* __restrict__ b2,
                     const float* __restrict__ W3, const float* __restrict__ b3,
                     float* __restrict__ out)
{
    extern __shared__ char sm[];
    uint32_t* VIh = (uint32_t*)(sm + OFF_VIH);
    uint32_t* VJh = (uint32_t*)(sm + OFF_VJH);
    uint32_t* W1F = (uint32_t*)(sm + OFF_W1F);
    uint32_t* W2F = (uint32_t*)(sm + OFF_W2F);
    float*    B1S = (float*)(sm + OFF_B1S);
    float*    B2S = (float*)(sm + OFF_B2S);
    float*    W3S = (float*)(sm + OFF_W3S);

    const int tid  = threadIdx.x;
    const int wid  = tid >> 5;
    const int lane = tid & 31;
    const int g    = lane >> 2;   // groupID (row within fragment)
    const int t    = lane & 3;    // threadID_in_group
    const int b    = blockIdx.y;

    // decode (ti, tj), ti <= tj
    int rem = blockIdx.x;
    int ti = 0;
    while (rem >= NT - ti) { rem -= NT - ti; ti++; }
    const int tj = ti + rem;

    // ---- load v tiles (64 x 128 fp32), convert to half2, rows padded to 68 u32 ----
    const float* vb = v + (size_t)b * NN * DD;
    for (int e = tid; e < 64 * 32; e += THREADS) {
        int r = e >> 5, c = e & 31;
        float4 xi = ((const float4*)(vb + (size_t)(ti * 64 + r) * DD))[c];
        float4 xj = ((const float4*)(vb + (size_t)(tj * 64 + r) * DD))[c];
        VIh[r * 68 + 2 * c]     = packh2(xi.x, xi.y);
        VIh[r * 68 + 2 * c + 1] = packh2(xi.z, xi.w);
        VJh[r * 68 + 2 * c]     = packh2(xj.x, xj.y);
        VJh[r * 68 + 2 * c + 1] = packh2(xj.z, xj.w);
    }
    // ---- W1 half2 fragments: [ks(8)][lane(32)][n(8)x{b0,b1}] ----
    for (int idx = tid; idx < 8 * 32 * 16; idx += THREADS) {
        int ks = idx >> 9, ln = (idx >> 4) & 31, rm = idx & 15;
        int n = rm >> 1, e = rm & 1;
        int o  = (ln >> 2) + 8 * n;
        int kb = 16 * ks + 2 * (ln & 3) + 8 * e;
        W1F[idx] = packh2(W1[o * DD + kb], W1[o * DD + kb + 1]);
    }
    // ---- W2 half2 fragments: [ks(4)][lane(32)][n(4)x{b0,b1}] ----
    for (int idx = tid; idx < 4 * 32 * 8; idx += THREADS) {
        int ks = idx >> 8, ln = (idx >> 3) & 31, rm = idx & 7;
        int n = rm >> 1, e = rm & 1;
        int o  = (ln >> 2) + 8 * n;
        int kb = 16 * ks + 2 * (ln & 3) + 8 * e;
        W2F[idx] = packh2(W2[o * H1C + kb], W2[o * H1C + kb + 1]);
    }
    if (tid < H1C) B1S[tid] = b1[tid];
    if (tid < H2C) B2S[tid] = b2[tid];
    if (tid < H2C) W3S[tid] = W3[tid];
    const float bias3 = b3[0];
    __syncthreads();

    float* ob = out + (size_t)b * NN * NN;

    for (int ip = 0; ip < 2; ++ip) {
        const int il0 = wid * 8 + ip * 4;     // first of 4 i-rows
        const int ig0 = ti * 64 + il0;

        // hoist 4 i-rows' half2 values at this thread's k-positions (64 regs)
        uint32_t vlo[4][8], vhi[4][8];
        #pragma unroll
        for (int r = 0; r < 4; ++r)
            #pragma unroll
            for (int ks = 0; ks < 8; ++ks) {
                vlo[r][ks] = VIh[(il0 + r) * 68 + 8 * ks + t];
                vhi[r][ks] = VIh[(il0 + r) * 68 + 8 * ks + t + 4];
            }

        for (int jm = 0; jm < 4; ++jm) {
            const uint32_t* vj0 = VJh + (jm * 16 + g) * 68;
            const uint32_t* vj1 = VJh + (jm * 16 + 8 + g) * 68;

            // ---- GEMM1 (4 i-rows): h1 = |vi - vj| @ W1^T,  K = 128 ----
            float c1[4][8][4];
            #pragma unroll
            for (int n = 0; n < 8; ++n) {
                float bb0 = B1S[8 * n + 2 * t];
                float bb1 = B1S[8 * n + 2 * t + 1];
                #pragma unroll
                for (int r = 0; r < 4; ++r) {
                    c1[r][n][0] = bb0;  c1[r][n][1] = bb1;
                    c1[r][n][2] = bb0;  c1[r][n][3] = bb1;
                }
            }
            #pragma unroll
            for (int ks = 0; ks < 8; ++ks) {
                uint32_t j0l = vj0[8 * ks + t];
                uint32_t j1l = vj1[8 * ks + t];
                uint32_t j0h = vj0[8 * ks + t + 4];
                uint32_t j1h = vj1[8 * ks + t + 4];
                uint32_t af[4][4];
                #pragma unroll
                for (int r = 0; r < 4; ++r) {
                    af[r][0] = habs2_sub(vlo[r][ks], j0l);
                    af[r][1] = habs2_sub(vlo[r][ks], j1l);
                    af[r][2] = habs2_sub(vhi[r][ks], j0h);
                    af[r][3] = habs2_sub(vhi[r][ks], j1h);
                }
                const uint32_t* wq = W1F + ks * 512 + lane * 16;
                #pragma unroll
                for (int n = 0; n < 8; ++n) {
                    uint32_t w0 = wq[2 * n], w1 = wq[2 * n + 1];
                    #pragma unroll
                    for (int r = 0; r < 4; ++r)
                        mma_f16(c1[r][n], af[r][0], af[r][1], af[r][2], af[r][3], w0, w1);
                }
            }

            // ---- GEMM2 + epilogue in row-pairs (bounds register pressure) ----
            #pragma unroll
            for (int rp = 0; rp < 2; ++rp) {
                float c2[2][4][4];
                #pragma unroll
                for (int n = 0; n < 4; ++n) {
                    float bb0 = B2S[8 * n + 2 * t];
                    float bb1 = B2S[8 * n + 2 * t + 1];
                    #pragma unroll
                    for (int r2 = 0; r2 < 2; ++r2) {
                        c2[r2][n][0] = bb0;  c2[r2][n][1] = bb1;
                        c2[r2][n][2] = bb0;  c2[r2][n][3] = bb1;
                    }
                }
                #pragma unroll
                for (int ks = 0; ks < 4; ++ks) {
                    const uint32_t* wq = W2F + ks * 256 + lane * 8;
                    #pragma unroll
                    for (int r2 = 0; r2 < 2; ++r2) {
                        const int r = 2 * rp + r2;
                        uint32_t a0 = packh2(leaky(c1[r][2 * ks][0]),     leaky(c1[r][2 * ks][1]));
                        uint32_t a1 = packh2(leaky(c1[r][2 * ks][2]),     leaky(c1[r][2 * ks][3]));
                        uint32_t a2 = packh2(leaky(c1[r][2 * ks + 1][0]), leaky(c1[r][2 * ks + 1][1]));
                        uint32_t a3 = packh2(leaky(c1[r][2 * ks + 1][2]), leaky(c1[r][2 * ks + 1][3]));
                        #pragma unroll
                        for (int n = 0; n < 4; ++n)
                            mma_f16(c2[r2][n], a0, a1, a2, a3, wq[2 * n], wq[2 * n + 1]);
                    }
                }

                // ---- layer 3 + quad reductions, 2 rows ----
                float w3a[8];
                #pragma unroll
                for (int n = 0; n < 4; ++n) {
                    w3a[2 * n]     = W3S[8 * n + 2 * t];
                    w3a[2 * n + 1] = W3S[8 * n + 2 * t + 1];
                }
                #pragma unroll
                for (int r2 = 0; r2 < 2; ++r2) {
                    float p0 = 0.0f, p1 = 0.0f;
                    #pragma unroll
                    for (int n = 0; n < 4; ++n) {
                        p0 += leaky(c2[r2][n][0]) * w3a[2 * n];
                        p0 += leaky(c2[r2][n][1]) * w3a[2 * n + 1];
                        p1 += leaky(c2[r2][n][2]) * w3a[2 * n];
                        p1 += leaky(c2[r2][n][3]) * w3a[2 * n + 1];
                    }
                    p0 += __shfl_xor_sync(0xFFFFFFFFu, p0, 1);
                    p0 += __shfl_xor_sync(0xFFFFFFFFu, p0, 2);
                    p1 += __shfl_xor_sync(0xFFFFFFFFu, p1, 1);
                    p1 += __shfl_xor_sync(0xFFFFFFFFu, p1, 2);

                    if (t == 0) {
                        const int ig = ig0 + 2 * rp + r2;
                        const int jg = tj * 64 + jm * 16 + g;
                        float v0 = p0 + bias3, v1 = p1 + bias3;
                        ob[(size_t)ig * NN + jg]     = v0;
                        ob[(size_t)ig * NN + jg + 8] = v1;
                        if (ti != tj) {   // mirror (logits exactly symmetric)
                            ob[(size_t)jg * NN + ig]       = v0;
                            ob[(size_t)(jg + 8) * NN + ig] = v1;
                        }
                    }
                }
            }
        }
    }
}

// ---------------------------------------------------------------------------
// Row softmax over last axis. One block (128 thr) per (b, i); float4 I/O.
// ---------------------------------------------------------------------------
__global__ __launch_bounds__(128)
void adj_softmax_kernel(float* __restrict__ out)
{
    float4* __restrict__ p = (float4*)(out + (size_t)blockIdx.x * NN);
    const int tid = threadIdx.x;

    float4 x = p[tid];

    float m = fmaxf(fmaxf(x.x, x.y), fmaxf(x.z, x.w));
    #pragma unroll
    for (int o = 16; o; o >>= 1) m = fmaxf(m, __shfl_xor_sync(0xFFFFFFFFu, m, o));
    __shared__ float redm[4];
    if ((tid & 31) == 0) redm[tid >> 5] = m;
    __syncthreads();
    float M = fmaxf(fmaxf(redm[0], redm[1]), fmaxf(redm[2], redm[3]));

    float4 e;
    e.x = __expf(x.x - M);
    e.y = __expf(x.y - M);
    e.z = __expf(x.z - M);
    e.w = __expf(x.w - M);

    float s = (e.x + e.y) + (e.z + e.w);
    #pragma unroll
    for (int o = 16; o; o >>= 1) s += __shfl_xor_sync(0xFFFFFFFFu, s, o);
    __shared__ float reds[4];
    if ((tid & 31) == 0) reds[tid >> 5] = s;
    __syncthreads();
    float S = (reds[0] + reds[1]) + (reds[2] + reds[3]);

    float inv = __fdividef(1.0f, S);
    e.x *= inv; e.y *= inv; e.z *= inv; e.w *= inv;
    p[tid] = e;
}

extern "C" void kernel_launch(void* const* d_in, const int* in_sizes, int n_in,
                              void* d_out, int out_size)
{
    const float* v  = (const float*)d_in[0];
    const float* W1 = (const float*)d_in[1];
    const float* b1 = (const float*)d_in[2];
    const float* W2 = (const float*)d_in[3];
    const float* b2 = (const float*)d_in[4];
    const float* W3 = (const float*)d_in[5];
    const float* b3 = (const float*)d_in[6];
    float* out = (float*)d_out;

    cudaFuncSetAttribute(adj_hmma_kernel,
                         cudaFuncAttributeMaxDynamicSharedMemorySize, SMEM_TOTAL);

    dim3 grid(NPAIRS, NB);   // (36, 4) — one wave of 144 CTAs
    adj_hmma_kernel<<<grid, THREADS, SMEM_TOTAL>>>(v, W1, b1, W2, b2, W3, b3, out);
    adj_softmax_kernel<<<NB * NN, 128>>>(out);
}